// round 16
// baseline (speedup 1.0000x reference)
#include <cuda_runtime.h>
#include <math.h>

// Shapes (fixed by the problem)
#define BATCH 4
#define CHN   32
#define HDIM  256
#define WDIM  256
#define PLANE (HDIM * WDIM)           // 65536
#define NPIX  (BATCH * PLANE)         // 262144
#define NROWS (BATCH * CHN * HDIM)    // 32768 rows (W pass)
#define NEL   (BATCH * CHN * PLANE)   // 8388608 complex elements

typedef unsigned long long ull;

// ---------- global scratch / tables (static device memory only) ----------
__device__ float4 g_scratch4[NEL / 2];          // complex scratch (float2 pairs)
__device__ float  g_mag[NEL];                   // magnitude plane (non-identity mag path)
__device__ float2 g_c1f[256];                   // chirp c1
__device__ float2 g_s1f[256];                   // c1 * scale (output side)
__device__ float2 g_c2f[256];                   // kernel chirp c2
__device__ float2 g_wf[256];                    // W256 twiddles
__device__ int    g_hasphase;                   // any nonzero phase weight?
__device__ int    g_ident;                      // magnitude block == identity?

// ---------- FFMA-imm add/sub (sm_103a: src1-imm FFMA has rt_SMSP=1 vs 2 for
// FADD / 3-reg FFMA — 2x issue rate). a*1.0+b and b*(-1.0)+a are EXACT.
static __device__ __forceinline__ float addi(float a, float b) {
    float r;
    asm("fma.rn.f32 %0, %1, 0F3F800000, %2;" : "=f"(r) : "f"(a), "f"(b));
    return r;
}
static __device__ __forceinline__ float subi(float a, float b) {  // a - b
    float r;
    asm("fma.rn.f32 %0, %1, 0FBF800000, %2;" : "=f"(r) : "f"(b), "f"(a));
    return r;
}

// ---------- complex helpers ----------
static __device__ __forceinline__ float2 cmul(float2 a, float2 b) {
    return make_float2(fmaf(a.x, b.x, -(a.y * b.y)), fmaf(a.x, b.y, a.y * b.x));
}
static __device__ __forceinline__ float2 cadd(float2 a, float2 b) {
    return make_float2(addi(a.x, b.x), addi(a.y, b.y));
}
static __device__ __forceinline__ float2 csub(float2 a, float2 b) {
    return make_float2(subi(a.x, b.x), subi(a.y, b.y));
}

// ---------- packed f32x2 helpers (conv kernels only) ----------
static __device__ __forceinline__ ull pack2(float a, float b) {
    ull r;
    asm("mov.b64 %0, {%1, %2};" : "=l"(r) : "f"(a), "f"(b));
    return r;
}
static __device__ __forceinline__ void fma2(ull& d, ull a, ull b) {
    asm("fma.rn.f32x2 %0, %1, %2, %0;" : "+l"(d) : "l"(a), "l"(b));
}
static __device__ __forceinline__ void unpack2(ull v, float& a, float& b) {
    asm("mov.b64 {%0, %1}, %2;" : "=f"(a), "=f"(b) : "l"(v));
}

// ---------- register DFT-16: DIF radix-2, natural in, bit-reversed out ----------
// Butterfly adds use FFMA-imm; constant twiddles are float literals (ptxas
// encodes them as FFMA/FMUL immediate forms on sm_103a — no cbank operand).
template <int S>
static __device__ __forceinline__ void fft16(float2* r) {
    const float sg = (float)S;
    const float C16[8] = {1.0f, 0.923879533f, 0.707106781f, 0.382683432f,
                          0.0f, -0.382683432f, -0.707106781f, -0.923879533f};
    const float S16[8] = {0.0f, 0.382683432f, 0.707106781f, 0.923879533f,
                          1.0f, 0.923879533f, 0.707106781f, 0.382683432f};
#pragma unroll
    for (int j = 0; j < 8; j++) {
        float2 u = r[j], v = r[j + 8];
        float2 d = csub(u, v);
        r[j] = cadd(u, v);
        r[j + 8] = (j == 0) ? d : cmul(d, make_float2(C16[j], sg * S16[j]));
    }
    const float C8[4] = {1.0f, 0.707106781f, 0.0f, -0.707106781f};
    const float S8[4] = {0.0f, 0.707106781f, 1.0f, 0.707106781f};
#pragma unroll
    for (int b = 0; b < 16; b += 8) {
#pragma unroll
        for (int j = 0; j < 4; j++) {
            float2 u = r[b + j], v = r[b + j + 4];
            float2 d = csub(u, v);
            r[b + j] = cadd(u, v);
            r[b + j + 4] = (j == 0) ? d : cmul(d, make_float2(C8[j], sg * S8[j]));
        }
    }
#pragma unroll
    for (int b = 0; b < 16; b += 4) {
        {
            float2 u = r[b], v = r[b + 2];
            r[b] = cadd(u, v);
            r[b + 2] = csub(u, v);
        }
        {
            float2 u = r[b + 1], v = r[b + 3];
            float2 d = csub(u, v);
            r[b + 1] = cadd(u, v);
            r[b + 3] = make_float2(-sg * d.y, sg * d.x);
        }
    }
#pragma unroll
    for (int b = 0; b < 16; b += 2) {
        float2 u = r[b], v = r[b + 1];
        r[b] = cadd(u, v);
        r[b + 1] = csub(u, v);
    }
}

// per-group shared region stride (8 groups/block; 272 used, 274 staggers banks)
#define GS 274

// core: r[] preloaded with u at natural positions i = 16*n1 + t.
// Produces y = ifft(fft(u)*c2): r[j] = y[m], m = t + 16*brev4(j).
// gbuf = this group's GS-float2 region (transpose pad). All exchanges stay
// within one half-warp group -> __syncwarp-only fencing.
// c2 multiply done in place via brev4-involution pair swaps (no extra array).
static __device__ __forceinline__ void frft_core(float2* r, float2* gbuf, int t,
                                                 const float2* sw) {
    const int BR[16] = {0, 8, 4, 12, 2, 10, 6, 14, 1, 9, 5, 13, 3, 11, 7, 15};

    // ---- forward FFT stage 1
    fft16<-1>(r);
#pragma unroll
    for (int j = 0; j < 16; j++) {
        int k1 = BR[j];
        float2 v = r[j];
        int m = (t * k1) & 255;
        if (m) v = cmul(v, sw[m]);
        gbuf[k1 * 17 + t] = v;
    }
    __syncwarp();

    // ---- forward FFT stage 2
#pragma unroll
    for (int n2 = 0; n2 < 16; n2++) r[n2] = gbuf[t * 17 + n2];
    __syncwarp();
    fft16<-1>(r);

    // ---- c2 multiply + in-place bit-reverse permute (brev4 is an involution):
    // dest slot d gets old r[BR[d]] * c2[t + 16*d]
#define C2M(RR, IDX) cmul((RR), __ldg(g_c2f + t + 16 * (IDX)))
    r[0]  = C2M(r[0], 0);
    r[6]  = C2M(r[6], 6);
    r[9]  = C2M(r[9], 9);
    r[15] = C2M(r[15], 15);
#define SWPC2(J, K) { float2 tj = C2M(r[(K)], J); float2 tk = C2M(r[(J)], K); \
                      r[(J)] = tj; r[(K)] = tk; }
    SWPC2(1, 8) SWPC2(2, 4) SWPC2(3, 12) SWPC2(5, 10) SWPC2(7, 14) SWPC2(11, 13)
#undef SWPC2
#undef C2M

    // ---- inverse FFT stage 1
    fft16<1>(r);
#pragma unroll
    for (int j = 0; j < 16; j++) {
        int k1 = BR[j];
        float2 v = r[j];
        int m = (t * k1) & 255;
        if (m) {
            float2 wv = sw[m];
            v = cmul(v, make_float2(wv.x, -wv.y));
        }
        gbuf[k1 * 17 + t] = v;
    }
    __syncwarp();

    // ---- inverse FFT stage 2
#pragma unroll
    for (int n2 = 0; n2 < 16; n2++) r[n2] = gbuf[t * 17 + n2];
    __syncwarp();   // group's pad reads drained -> caller may rewrite gbuf
    fft16<1>(r);
}

// ---------- kernel 0: chirp / twiddle tables + weight-structure flags ----------
__global__ void k_init(const float* __restrict__ alpha, const float* __restrict__ w) {
    int i = threadIdx.x;  // 256 threads
    float a = fminf(fmaxf(alpha[0], 1e-4f), 2.0f - 1e-4f);
    float s4, c4;
    sincospif(a * 0.25f, &s4, &c4);
    float tan_a2 = s4 / c4;                 // tan(a*pi/4)
    float sin_a = sinpif(a * 0.5f);         // sin(a*pi/2)
    float scale = 1.0f / (256.0f * sqrtf(fabsf(sin_a) + 1e-12f));
    float n = (float)(i - 128);
    float n2 = n * n;
    float s, c;
    sincospif(-n2 * tan_a2 * (1.0f / 256.0f), &s, &c);
    g_c1f[i] = make_float2(c, s);
    g_s1f[i] = make_float2(c * scale, s * scale);
    sincospif(-n2 / (256.0f * sin_a), &s, &c);
    g_c2f[i] = make_float2(c, s);
    sincospif(-(float)i * (2.0f / 256.0f), &s, &c);
    g_wf[i] = make_float2(c, s);

    // weight structure: any nonzero phase weight? magnitude block == identity?
    int anyp = 0, nonid = 0;
#pragma unroll
    for (int idx = i; idx < CHN * CHN; idx += 256) {
        int o = idx >> 5, cc = idx & 31;
        anyp |= (w[o * 64 + 32 + cc] != 0.0f);
        float expect = (o == cc) ? 1.0f : 0.0f;
        nonid |= (w[o * 64 + cc] != expect);
    }
    int hp = __syncthreads_or(anyp);
    int ni = __syncthreads_or(nonid);
    if (i == 0) {
        g_hasphase = hp;
        g_ident = !ni;
    }
}

// ---------- kernel 1: FRFT along W (rows). 8 rows/block, 128 threads.
// Direct global gather (i = 16*n1+t is contiguous over t) and direct coalesced
// scatter (m = t+16*BR[j] contiguous over t) — NO shared staging round trips.
__global__ void __launch_bounds__(128) k_frft_w(const float* __restrict__ x) {
    __shared__ float2 pad[8 * GS];                  // 17.5 KB
    __shared__ float2 sw[256];                      // 2 KB
    float2* scr = reinterpret_cast<float2*>(g_scratch4);

    int tid = threadIdx.x;
    sw[tid] = g_wf[tid];
    sw[tid + 128] = g_wf[tid + 128];

    int t = tid & 15, g = tid >> 4;
    int row = blockIdx.x * 8 + g;
    const float* xr = x + row * 256;

    float2 r[16];
#pragma unroll
    for (int n1 = 0; n1 < 16; n1++) {
        int i = 16 * n1 + t;
        int src = (i + 128) & 255;                  // ifftshift
        float xv = xr[src];
        float2 c1 = __ldg(g_c1f + i);
        r[n1] = make_float2(xv * c1.x, xv * c1.y);
    }
    __syncthreads();   // sw table ready (global loads above hid the fill)

    frft_core(r, pad + g * GS, t, sw);

    const int BR[16] = {0, 8, 4, 12, 2, 10, 6, 14, 1, 9, 5, 13, 3, 11, 7, 15};
    float2* sr = scr + row * 256;
#pragma unroll
    for (int j = 0; j < 16; j++) {
        int m = t + 16 * BR[j];
        float2 v = cmul(r[j], __ldg(g_s1f + m));
        sr[(m + 128) & 255] = v;                    // fftshift; contiguous over t
    }
}

// ---------- fast magnitude / atan2 ----------
static __device__ __forceinline__ float fast_mag(float x, float y) {
    float z2 = fmaf(x, x, y * y);
    float rs;
    asm("rsqrt.approx.f32 %0, %1;" : "=f"(rs) : "f"(z2));
    float m = z2 * rs;
    return (z2 > 0.0f) ? m : 0.0f;
}
static __device__ __forceinline__ float fast_atan2(float y, float x) {
    float ax = fabsf(x), ay = fabsf(y);
    float mx = fmaxf(ax, ay), mn = fminf(ax, ay);
    float rc;
    asm("rcp.approx.f32 %0, %1;" : "=f"(rc) : "f"(mx));
    float t = mn * rc;
    t = (mx == 0.0f) ? 0.0f : t;
    float s = t * t;
    float p = -0.0117212f;
    p = fmaf(p, s, 0.05265332f);
    p = fmaf(p, s, -0.11643287f);
    p = fmaf(p, s, 0.19354346f);
    p = fmaf(p, s, -0.33262347f);
    p = fmaf(p, s, 0.99997726f);
    float r = t * p;
    if (ay > ax) r = 1.57079632679f - r;
    if (x < 0.0f) r = 3.14159265359f - r;
    return copysignf(r, y);
}

// ---------- kernel 2: FRFT along H (columns), in place, 8-col tiles.
// Output mode by weight structure:
//   hasphase          -> complex to scr (k_conv_fb finishes)
//   !hasphase & ident -> |Y| straight into d_out (conv is identity: DONE here)
//   !hasphase         -> |Y| into g_mag (k_conv_fb finishes)
__global__ void __launch_bounds__(128) k_frft_h(float* __restrict__ out) {
    __shared__ float2 buf[8 * GS];                  // aliased nat+pad per group
    __shared__ float2 sw[256];
    float2* scr = reinterpret_cast<float2*>(g_scratch4);

    int tid = threadIdx.x;
    sw[tid] = g_wf[tid];
    sw[tid + 128] = g_wf[tid + 128];
    int hp = g_hasphase;
    int id = g_ident;

    int plane = blockIdx.x >> 5;          // 0..127  (b*C + c)
    int w0 = (blockIdx.x & 31) * 8;       // column tile
    int pbase = plane * PLANE;

    // load 256(h) x 8(w) tile, ifftshift along h, multiply c1[h]
#pragma unroll
    for (int k = 0; k < 16; k++) {
        int e = tid + 128 * k;   // 0..2047
        int h = e >> 3, wq = e & 7;
        float2 v = scr[pbase + ((h + 128) & 255) * 256 + w0 + wq];
        buf[wq * GS + h] = cmul(v, __ldg(g_c1f + h));   // broadcast ldg (same h per 8)
    }
    __syncthreads();   // staging + sw table ready

    int t = tid & 15, g = tid >> 4;  // g = column within tile
    float2* gbuf = buf + g * GS;
    float2 r[16];
#pragma unroll
    for (int n1 = 0; n1 < 16; n1++) r[n1] = gbuf[16 * n1 + t];
    __syncwarp();      // group reads drained before core's pad writes alias them

    frft_core(r, gbuf, t, sw);

    const int BR[16] = {0, 8, 4, 12, 2, 10, 6, 14, 1, 9, 5, 13, 3, 11, 7, 15};
#pragma unroll
    for (int j = 0; j < 16; j++) {
        int m = t + 16 * BR[j];
        float2 v = cmul(r[j], __ldg(g_s1f + m));
        if (hp)
            gbuf[(m + 128) & 255] = v;
        else
            gbuf[(m + 128) & 255] = make_float2(fast_mag(v.x, v.y), 0.0f);
    }
    __syncthreads();

    // coalesced global write-back (in place)
    if (hp) {
#pragma unroll
        for (int k = 0; k < 16; k++) {
            int e = tid + 128 * k;
            int o = e >> 3, wq = e & 7;
            scr[pbase + o * 256 + w0 + wq] = buf[wq * GS + o];
        }
    } else {
        // mag plane indexing == output indexing (b*C+c)*65536 + h*256 + w
        float* dst = id ? out : g_mag;
#pragma unroll
        for (int k = 0; k < 16; k++) {
            int e = tid + 128 * k;
            int o = e >> 3, wq = e & 7;
            dst[pbase + o * 256 + w0 + wq] = buf[wq * GS + o].x;
        }
    }
}

// ---------- kernel 3: merged conv fallback (single launch; exits on identity path)
__global__ void __launch_bounds__(256, 3) k_conv_fb(const float* __restrict__ w,
                                                    float* __restrict__ out) {
    int hp = g_hasphase;
    if (!hp && g_ident) return;            // identity fast path: k_frft_h already wrote out

    __shared__ ull wsm[CHN * 16];
    __shared__ ull wsp[CHN * 16];
    const float INV_PI = 0.318309886f;
    int tid = threadIdx.x;
#pragma unroll
    for (int i = tid; i < CHN * 16; i += 256) {
        int c = i >> 4, op = i & 15;
        wsm[i] = pack2(w[(2 * op) * 64 + c], w[(2 * op + 1) * 64 + c]);
        wsp[i] = pack2(w[(2 * op) * 64 + 32 + c] * INV_PI,
                       w[(2 * op + 1) * 64 + 32 + c] * INV_PI);
    }
    __syncthreads();

    int pix = blockIdx.x * 256 + tid;
    int b = pix >> 16;
    int hw = pix & 65535;

    ull acc[16];
#pragma unroll
    for (int op = 0; op < 16; op++) acc[op] = 0ULL;

    if (hp) {
        const float2* Y = reinterpret_cast<const float2*>(g_scratch4);
        const float2* base = Y + b * (CHN * PLANE) + hw;
#pragma unroll 2
        for (int c = 0; c < CHN; c++) {
            float2 z = base[c * PLANE];
            float m = fast_mag(z.x, z.y);
            float ph = fast_atan2(z.y, z.x);
            ull mm = pack2(m, m);
            ull pp = pack2(ph, ph);
            const ulonglong2* rm = reinterpret_cast<const ulonglong2*>(wsm + (c << 4));
            const ulonglong2* rp = reinterpret_cast<const ulonglong2*>(wsp + (c << 4));
#pragma unroll
            for (int q = 0; q < 8; q++) {
                ulonglong2 wvm = rm[q];
                ulonglong2 wvp = rp[q];
                fma2(acc[2 * q],     wvm.x, mm);
                fma2(acc[2 * q + 1], wvm.y, mm);
                fma2(acc[2 * q],     wvp.x, pp);
                fma2(acc[2 * q + 1], wvp.y, pp);
            }
        }
    } else {
        const float* base = g_mag + b * (CHN * PLANE) + hw;
#pragma unroll 4
        for (int c = 0; c < CHN; c++) {
            float m = base[c * PLANE];
            ull mm = pack2(m, m);
            const ulonglong2* rm = reinterpret_cast<const ulonglong2*>(wsm + (c << 4));
#pragma unroll
            for (int q = 0; q < 8; q++) {
                ulonglong2 wv = rm[q];
                fma2(acc[2 * q],     wv.x, mm);
                fma2(acc[2 * q + 1], wv.y, mm);
            }
        }
    }

    float* ob = out + b * (CHN * PLANE) + hw;
#pragma unroll
    for (int op = 0; op < 16; op++) {
        float a0, a1;
        unpack2(acc[op], a0, a1);
        ob[(2 * op) * PLANE] = a0;
        ob[(2 * op + 1) * PLANE] = a1;
    }
}

// ---------- launcher ----------
extern "C" void kernel_launch(void* const* d_in, const int* in_sizes, int n_in,
                              void* d_out, int out_size) {
    const float* x = nullptr;
    const float* alpha = nullptr;
    const float* w = nullptr;
    for (int i = 0; i < n_in; i++) {
        if (in_sizes[i] == 1)
            alpha = (const float*)d_in[i];
        else if (in_sizes[i] == CHN * 2 * CHN)
            w = (const float*)d_in[i];
        else
            x = (const float*)d_in[i];
    }
    float* out = (float*)d_out;

    k_init<<<1, 256>>>(alpha, w);
    k_frft_w<<<NROWS / 8, 128>>>(x);
    k_frft_h<<<(BATCH * CHN * WDIM) / 8, 128>>>(out);
    k_conv_fb<<<NPIX / 256, 256>>>(w, out);
}

// round 17
// speedup vs baseline: 1.0294x; 1.0294x over previous
#include <cuda_runtime.h>
#include <math.h>

// Shapes (fixed by the problem)
#define BATCH 4
#define CHN   32
#define HDIM  256
#define WDIM  256
#define PLANE (HDIM * WDIM)           // 65536
#define NPIX  (BATCH * PLANE)         // 262144
#define NROWS (BATCH * CHN * HDIM)    // 32768 rows (W pass)
#define NEL   (BATCH * CHN * PLANE)   // 8388608 complex elements

typedef unsigned long long ull;

// ---------- global scratch / tables (static device memory only) ----------
__device__ float4 g_scratch4[NEL / 2];          // complex scratch (float2 pairs)
__device__ float  g_mag[NEL];                   // magnitude plane (non-identity mag path)
__device__ float2 g_c1f[256];                   // chirp c1
__device__ float2 g_s1f[256];                   // c1 * scale (output side)
__device__ float2 g_c2f[256];                   // kernel chirp c2
__device__ float2 g_wf[256];                    // W256 twiddles
__device__ int    g_hasphase;                   // any nonzero phase weight?
__device__ int    g_ident;                      // magnitude block == identity?

// ---------- packed f32x2 helpers ----------
static __device__ __forceinline__ ull pack2(float a, float b) {
    ull r;
    asm("mov.b64 %0, {%1, %2};" : "=l"(r) : "f"(a), "f"(b));
    return r;
}
static __device__ __forceinline__ void unpack2(ull v, float& a, float& b) {
    asm("mov.b64 {%0, %1}, %2;" : "=f"(a), "=f"(b) : "l"(v));
}
static __device__ __forceinline__ ull dupf(float f) {
    unsigned u = __float_as_uint(f);
    return ((ull)u << 32) | u;
}
static __device__ __forceinline__ ull add2(ull a, ull b) {
    ull r; asm("add.rn.f32x2 %0, %1, %2;" : "=l"(r) : "l"(a), "l"(b)); return r;
}
static __device__ __forceinline__ ull fma2v(ull a, ull b, ull c) {
    ull r; asm("fma.rn.f32x2 %0, %1, %2, %3;" : "=l"(r) : "l"(a), "l"(b), "l"(c)); return r;
}
static __device__ __forceinline__ ull sub2(ull a, ull b) {   // a - b (exact: b*(-1)+a)
    return fma2v(b, dupf(-1.0f), a);
}
// accumulate form (conv kernels)
static __device__ __forceinline__ void fma2(ull& d, ull a, ull b) {
    asm("fma.rn.f32x2 %0, %1, %2, %0;" : "+l"(d) : "l"(a), "l"(b));
}

// ---------- complex values packed as ull: lo = re, hi = im ----------
// Twiddle multiplies unpack to scalar FFMA and repack; the halves already sit
// in an aligned register pair so the mov.b64 pair mostly folds away in SASS.
static __device__ __forceinline__ ull cmul_t(ull a, float2 b) {      // a * b
    float ax, ay;
    unpack2(a, ax, ay);
    return pack2(fmaf(ax, b.x, -(ay * b.y)), fmaf(ax, b.y, ay * b.x));
}
static __device__ __forceinline__ ull cmul_tc(ull a, float2 b) {     // a * conj(b)
    float ax, ay;
    unpack2(a, ax, ay);
    return pack2(fmaf(ax, b.x, ay * b.y), fmaf(ay, b.x, -(ax * b.y)));
}
// scalar float2 complex mul (staging paths)
static __device__ __forceinline__ float2 cmul(float2 a, float2 b) {
    return make_float2(fmaf(a.x, b.x, -(a.y * b.y)), fmaf(a.x, b.y, a.y * b.x));
}

// ---------- packed register DFT-16: DIF radix-2, natural in, bit-reversed out ----
// Butterfly adds/subs are ONE f32x2 instruction each (was two FADDs): per-lane
// rounding identical to scalar -> bit-identical results.
template <int S>
static __device__ __forceinline__ void fft16u(ull* r) {
    const float sg = (float)S;
    const float C16[8] = {1.0f, 0.923879533f, 0.707106781f, 0.382683432f,
                          0.0f, -0.382683432f, -0.707106781f, -0.923879533f};
    const float S16[8] = {0.0f, 0.382683432f, 0.707106781f, 0.923879533f,
                          1.0f, 0.923879533f, 0.707106781f, 0.382683432f};
#pragma unroll
    for (int j = 0; j < 8; j++) {
        ull u = r[j], v = r[j + 8];
        ull d = sub2(u, v);
        r[j] = add2(u, v);
        r[j + 8] = (j == 0) ? d : cmul_t(d, make_float2(C16[j], sg * S16[j]));
    }
    const float C8[4] = {1.0f, 0.707106781f, 0.0f, -0.707106781f};
    const float S8[4] = {0.0f, 0.707106781f, 1.0f, 0.707106781f};
#pragma unroll
    for (int b = 0; b < 16; b += 8) {
#pragma unroll
        for (int j = 0; j < 4; j++) {
            ull u = r[b + j], v = r[b + j + 4];
            ull d = sub2(u, v);
            r[b + j] = add2(u, v);
            r[b + j + 4] = (j == 0) ? d : cmul_t(d, make_float2(C8[j], sg * S8[j]));
        }
    }
#pragma unroll
    for (int b = 0; b < 16; b += 4) {
        {
            ull u = r[b], v = r[b + 2];
            r[b] = add2(u, v);
            r[b + 2] = sub2(u, v);
        }
        {
            ull u = r[b + 1], v = r[b + 3];
            ull d = sub2(u, v);
            r[b + 1] = add2(u, v);
            float dx, dy;
            unpack2(d, dx, dy);
            r[b + 3] = pack2(-sg * dy, sg * dx);    // * (0, sg)
        }
    }
#pragma unroll
    for (int b = 0; b < 16; b += 2) {
        ull u = r[b], v = r[b + 1];
        r[b] = add2(u, v);
        r[b + 1] = sub2(u, v);
    }
}

// per-group shared region stride (8 groups/block; 272 used, 274 staggers banks)
#define GS 274

// core: r[] preloaded (packed) with u at natural positions i = 16*n1 + t.
// Produces y = ifft(fft(u)*c2): r[j] = y[m], m = t + 16*brev4(j).
// gbuf = this group's GS-ull region (transpose pad). All exchanges stay within
// one half-warp group -> __syncwarp-only fencing.
// c2 multiply done in place via brev4-involution pair swaps (no extra array).
static __device__ __forceinline__ void frft_core(ull* r, ull* gbuf, int t,
                                                 const float2* sw) {
    const int BR[16] = {0, 8, 4, 12, 2, 10, 6, 14, 1, 9, 5, 13, 3, 11, 7, 15};

    // ---- forward FFT stage 1
    fft16u<-1>(r);
#pragma unroll
    for (int j = 0; j < 16; j++) {
        int k1 = BR[j];
        ull v = r[j];
        int m = (t * k1) & 255;
        if (m) v = cmul_t(v, sw[m]);
        gbuf[k1 * 17 + t] = v;
    }
    __syncwarp();

    // ---- forward FFT stage 2
#pragma unroll
    for (int n2 = 0; n2 < 16; n2++) r[n2] = gbuf[t * 17 + n2];
    __syncwarp();
    fft16u<-1>(r);

    // ---- c2 multiply + in-place bit-reverse permute (brev4 is an involution):
    // dest slot d gets old r[BR[d]] * c2[t + 16*d]
#define C2M(RR, IDX) cmul_t((RR), __ldg(g_c2f + t + 16 * (IDX)))
    r[0]  = C2M(r[0], 0);
    r[6]  = C2M(r[6], 6);
    r[9]  = C2M(r[9], 9);
    r[15] = C2M(r[15], 15);
#define SWPC2(J, K) { ull tj = C2M(r[(K)], J); ull tk = C2M(r[(J)], K); \
                      r[(J)] = tj; r[(K)] = tk; }
    SWPC2(1, 8) SWPC2(2, 4) SWPC2(3, 12) SWPC2(5, 10) SWPC2(7, 14) SWPC2(11, 13)
#undef SWPC2
#undef C2M

    // ---- inverse FFT stage 1
    fft16u<1>(r);
#pragma unroll
    for (int j = 0; j < 16; j++) {
        int k1 = BR[j];
        ull v = r[j];
        int m = (t * k1) & 255;
        if (m) v = cmul_tc(v, sw[m]);
        gbuf[k1 * 17 + t] = v;
    }
    __syncwarp();

    // ---- inverse FFT stage 2
#pragma unroll
    for (int n2 = 0; n2 < 16; n2++) r[n2] = gbuf[t * 17 + n2];
    __syncwarp();   // group's pad reads drained -> caller may rewrite gbuf
    fft16u<1>(r);
}

// ---------- kernel 0: chirp / twiddle tables + weight-structure flags ----------
__global__ void k_init(const float* __restrict__ alpha, const float* __restrict__ w) {
    int i = threadIdx.x;  // 256 threads
    float a = fminf(fmaxf(alpha[0], 1e-4f), 2.0f - 1e-4f);
    float s4, c4;
    sincospif(a * 0.25f, &s4, &c4);
    float tan_a2 = s4 / c4;                 // tan(a*pi/4)
    float sin_a = sinpif(a * 0.5f);         // sin(a*pi/2)
    float scale = 1.0f / (256.0f * sqrtf(fabsf(sin_a) + 1e-12f));
    float n = (float)(i - 128);
    float n2 = n * n;
    float s, c;
    sincospif(-n2 * tan_a2 * (1.0f / 256.0f), &s, &c);
    g_c1f[i] = make_float2(c, s);
    g_s1f[i] = make_float2(c * scale, s * scale);
    sincospif(-n2 / (256.0f * sin_a), &s, &c);
    g_c2f[i] = make_float2(c, s);
    sincospif(-(float)i * (2.0f / 256.0f), &s, &c);
    g_wf[i] = make_float2(c, s);

    // weight structure: any nonzero phase weight? magnitude block == identity?
    int anyp = 0, nonid = 0;
#pragma unroll
    for (int idx = i; idx < CHN * CHN; idx += 256) {
        int o = idx >> 5, cc = idx & 31;
        anyp |= (w[o * 64 + 32 + cc] != 0.0f);
        float expect = (o == cc) ? 1.0f : 0.0f;
        nonid |= (w[o * 64 + cc] != expect);
    }
    int hp = __syncthreads_or(anyp);
    int ni = __syncthreads_or(nonid);
    if (i == 0) {
        g_hasphase = hp;
        g_ident = !ni;
    }
}

// ---------- kernel 1: FRFT along W (rows). 8 rows/block, 128 threads.
// Direct global gather (i = 16*n1+t is contiguous over t) and direct coalesced
// scatter (m = t+16*BR[j] contiguous over t) — NO shared staging round trips.
__global__ void __launch_bounds__(128) k_frft_w(const float* __restrict__ x) {
    __shared__ ull pad[8 * GS];                     // 17.5 KB
    __shared__ float2 sw[256];                      // 2 KB
    ull* scru = reinterpret_cast<ull*>(g_scratch4); // (re,im) == packed layout

    int tid = threadIdx.x;
    sw[tid] = g_wf[tid];
    sw[tid + 128] = g_wf[tid + 128];

    int t = tid & 15, g = tid >> 4;
    int row = blockIdx.x * 8 + g;
    const float* xr = x + row * 256;

    ull r[16];
#pragma unroll
    for (int n1 = 0; n1 < 16; n1++) {
        int i = 16 * n1 + t;
        int src = (i + 128) & 255;                  // ifftshift
        float xv = xr[src];
        float2 c1 = __ldg(g_c1f + i);
        r[n1] = pack2(xv * c1.x, xv * c1.y);
    }
    __syncthreads();   // sw table ready (global loads above hid the fill)

    frft_core(r, pad + g * GS, t, sw);

    const int BR[16] = {0, 8, 4, 12, 2, 10, 6, 14, 1, 9, 5, 13, 3, 11, 7, 15};
    ull* sr = scru + row * 256;
#pragma unroll
    for (int j = 0; j < 16; j++) {
        int m = t + 16 * BR[j];
        sr[(m + 128) & 255] = cmul_t(r[j], __ldg(g_s1f + m));  // fftshift store
    }
}

// ---------- fast magnitude / atan2 ----------
static __device__ __forceinline__ float fast_mag(float x, float y) {
    float z2 = fmaf(x, x, y * y);
    float rs;
    asm("rsqrt.approx.f32 %0, %1;" : "=f"(rs) : "f"(z2));
    float m = z2 * rs;
    return (z2 > 0.0f) ? m : 0.0f;
}
static __device__ __forceinline__ float fast_atan2(float y, float x) {
    float ax = fabsf(x), ay = fabsf(y);
    float mx = fmaxf(ax, ay), mn = fminf(ax, ay);
    float rc;
    asm("rcp.approx.f32 %0, %1;" : "=f"(rc) : "f"(mx));
    float t = mn * rc;
    t = (mx == 0.0f) ? 0.0f : t;
    float s = t * t;
    float p = -0.0117212f;
    p = fmaf(p, s, 0.05265332f);
    p = fmaf(p, s, -0.11643287f);
    p = fmaf(p, s, 0.19354346f);
    p = fmaf(p, s, -0.33262347f);
    p = fmaf(p, s, 0.99997726f);
    float r = t * p;
    if (ay > ax) r = 1.57079632679f - r;
    if (x < 0.0f) r = 3.14159265359f - r;
    return copysignf(r, y);
}

// ---------- kernel 2: FRFT along H (columns), in place, 8-col tiles.
// Output mode by weight structure:
//   hasphase          -> complex to scr (k_conv_fb finishes)
//   !hasphase & ident -> |Y| straight into d_out (conv is identity: DONE here)
//   !hasphase         -> |Y| into g_mag (k_conv_fb finishes)
__global__ void __launch_bounds__(128) k_frft_h(float* __restrict__ out) {
    __shared__ ull buf[8 * GS];                     // aliased nat+pad per group
    __shared__ float2 sw[256];
    float2* scr = reinterpret_cast<float2*>(g_scratch4);
    ull* scru = reinterpret_cast<ull*>(g_scratch4);

    int tid = threadIdx.x;
    sw[tid] = g_wf[tid];
    sw[tid + 128] = g_wf[tid + 128];
    int hp = g_hasphase;
    int id = g_ident;

    int plane = blockIdx.x >> 5;          // 0..127  (b*C + c)
    int w0 = (blockIdx.x & 31) * 8;       // column tile
    int pbase = plane * PLANE;

    // load 256(h) x 8(w) tile, ifftshift along h, multiply c1[h]
#pragma unroll
    for (int k = 0; k < 16; k++) {
        int e = tid + 128 * k;   // 0..2047
        int h = e >> 3, wq = e & 7;
        float2 v = scr[pbase + ((h + 128) & 255) * 256 + w0 + wq];
        float2 u = cmul(v, __ldg(g_c1f + h));       // broadcast ldg (same h per 8)
        buf[wq * GS + h] = pack2(u.x, u.y);
    }
    __syncthreads();   // staging + sw table ready

    int t = tid & 15, g = tid >> 4;  // g = column within tile
    ull* gbuf = buf + g * GS;
    ull r[16];
#pragma unroll
    for (int n1 = 0; n1 < 16; n1++) r[n1] = gbuf[16 * n1 + t];
    __syncwarp();      // group reads drained before core's pad writes alias them

    frft_core(r, gbuf, t, sw);

    const int BR[16] = {0, 8, 4, 12, 2, 10, 6, 14, 1, 9, 5, 13, 3, 11, 7, 15};
#pragma unroll
    for (int j = 0; j < 16; j++) {
        int m = t + 16 * BR[j];
        ull v = cmul_t(r[j], __ldg(g_s1f + m));
        if (hp) {
            gbuf[(m + 128) & 255] = v;
        } else {
            float vx, vy;
            unpack2(v, vx, vy);
            gbuf[(m + 128) & 255] = pack2(fast_mag(vx, vy), 0.0f);
        }
    }
    __syncthreads();

    // coalesced global write-back (in place)
    if (hp) {
#pragma unroll
        for (int k = 0; k < 16; k++) {
            int e = tid + 128 * k;
            int o = e >> 3, wq = e & 7;
            scru[pbase + o * 256 + w0 + wq] = buf[wq * GS + o];
        }
    } else {
        // mag plane indexing == output indexing (b*C+c)*65536 + h*256 + w
        float* dst = id ? out : g_mag;
#pragma unroll
        for (int k = 0; k < 16; k++) {
            int e = tid + 128 * k;
            int o = e >> 3, wq = e & 7;
            float mv, dummy;
            unpack2(buf[wq * GS + o], mv, dummy);
            dst[pbase + o * 256 + w0 + wq] = mv;
        }
    }
}

// ---------- kernel 3: merged conv fallback (single launch; exits on identity path)
__global__ void __launch_bounds__(256, 3) k_conv_fb(const float* __restrict__ w,
                                                    float* __restrict__ out) {
    int hp = g_hasphase;
    if (!hp && g_ident) return;            // identity fast path: k_frft_h already wrote out

    __shared__ ull wsm[CHN * 16];
    __shared__ ull wsp[CHN * 16];
    const float INV_PI = 0.318309886f;
    int tid = threadIdx.x;
#pragma unroll
    for (int i = tid; i < CHN * 16; i += 256) {
        int c = i >> 4, op = i & 15;
        wsm[i] = pack2(w[(2 * op) * 64 + c], w[(2 * op + 1) * 64 + c]);
        wsp[i] = pack2(w[(2 * op) * 64 + 32 + c] * INV_PI,
                       w[(2 * op + 1) * 64 + 32 + c] * INV_PI);
    }
    __syncthreads();

    int pix = blockIdx.x * 256 + tid;
    int b = pix >> 16;
    int hw = pix & 65535;

    ull acc[16];
#pragma unroll
    for (int op = 0; op < 16; op++) acc[op] = 0ULL;

    if (hp) {
        const float2* Y = reinterpret_cast<const float2*>(g_scratch4);
        const float2* base = Y + b * (CHN * PLANE) + hw;
#pragma unroll 2
        for (int c = 0; c < CHN; c++) {
            float2 z = base[c * PLANE];
            float m = fast_mag(z.x, z.y);
            float ph = fast_atan2(z.y, z.x);
            ull mm = pack2(m, m);
            ull pp = pack2(ph, ph);
            const ulonglong2* rm = reinterpret_cast<const ulonglong2*>(wsm + (c << 4));
            const ulonglong2* rp = reinterpret_cast<const ulonglong2*>(wsp + (c << 4));
#pragma unroll
            for (int q = 0; q < 8; q++) {
                ulonglong2 wvm = rm[q];
                ulonglong2 wvp = rp[q];
                fma2(acc[2 * q],     wvm.x, mm);
                fma2(acc[2 * q + 1], wvm.y, mm);
                fma2(acc[2 * q],     wvp.x, pp);
                fma2(acc[2 * q + 1], wvp.y, pp);
            }
        }
    } else {
        const float* base = g_mag + b * (CHN * PLANE) + hw;
#pragma unroll 4
        for (int c = 0; c < CHN; c++) {
            float m = base[c * PLANE];
            ull mm = pack2(m, m);
            const ulonglong2* rm = reinterpret_cast<const ulonglong2*>(wsm + (c << 4));
#pragma unroll
            for (int q = 0; q < 8; q++) {
                ulonglong2 wv = rm[q];
                fma2(acc[2 * q],     wv.x, mm);
                fma2(acc[2 * q + 1], wv.y, mm);
            }
        }
    }

    float* ob = out + b * (CHN * PLANE) + hw;
#pragma unroll
    for (int op = 0; op < 16; op++) {
        float a0, a1;
        unpack2(acc[op], a0, a1);
        ob[(2 * op) * PLANE] = a0;
        ob[(2 * op + 1) * PLANE] = a1;
    }
}

// ---------- launcher ----------
extern "C" void kernel_launch(void* const* d_in, const int* in_sizes, int n_in,
                              void* d_out, int out_size) {
    const float* x = nullptr;
    const float* alpha = nullptr;
    const float* w = nullptr;
    for (int i = 0; i < n_in; i++) {
        if (in_sizes[i] == 1)
            alpha = (const float*)d_in[i];
        else if (in_sizes[i] == CHN * 2 * CHN)
            w = (const float*)d_in[i];
        else
            x = (const float*)d_in[i];
    }
    float* out = (float*)d_out;

    k_init<<<1, 256>>>(alpha, w);
    k_frft_w<<<NROWS / 8, 128>>>(x);
    k_frft_h<<<(BATCH * CHN * WDIM) / 8, 128>>>(out);
    k_conv_fb<<<NPIX / 256, 256>>>(w, out);
}